// round 13
// baseline (speedup 1.0000x reference)
#include <cuda_runtime.h>
#include <cuda_fp16.h>
#include <math.h>
#include <stdint.h>

#define BATCH 8
#define NTOK  1024
#define CDIM  768
#define NHEAD 12
#define HDIM  64
#define NTOTC 2304
#define MROWS 8192
#define L2E   1.44269504f

// -------- device-global scratch --------
__device__ __align__(16) __half g_xh[MROWS * CDIM];          // fp16 x
__device__ __align__(16) __half g_wh[NTOTC * CDIM];          // fp16 [Wq; Wkv]
// half2 paired bias tables (pre-scaled by log2e):
//  E[h][i] = (lo=T[2i],   hi=T[2i-1])   (for even gather index b)
//  O[h][i] = (lo=T[2i+1], hi=T[2i])     (for odd  gather index b)
#define BHI 2048
__device__ __align__(16) __half g_btE[NHEAD * BHI * 2];
__device__ __align__(16) __half g_btO[NHEAD * BHI * 2];
__device__ __align__(16) __half g_q [BATCH * NHEAD * NTOK * HDIM];  // pre-scaled by 0.125*log2e
__device__ __align__(16) __half g_k [BATCH * NHEAD * NTOK * HDIM];
__device__ __align__(16) __half g_vT[BATCH * NHEAD * HDIM * NTOK];  // [bh][dim][tok]

// ============================================================================
// helpers
// ============================================================================
__device__ __forceinline__ uint32_t smem_u32(const void* p) {
    uint32_t a;
    asm("{ .reg .u64 t; cvta.to.shared.u64 t, %1; cvt.u32.u64 %0, t; }"
        : "=r"(a) : "l"(p));
    return a;
}
__device__ __forceinline__ uint32_t h2pack(float a, float b) {
    __half2 h = __floats2half2_rn(a, b);
    return *reinterpret_cast<uint32_t*>(&h);
}
__device__ __forceinline__ uint32_t hadd2u(uint32_t a, uint32_t b) {
    uint32_t r;
    asm("add.f16x2 %0, %1, %2;" : "=r"(r) : "r"(a), "r"(b));
    return r;
}
__device__ __forceinline__ uint32_t ex2h2(uint32_t a) {
    uint32_t r;
    asm("ex2.approx.f16x2 %0, %1;" : "=r"(r) : "r"(a));
    return r;
}
__device__ __forceinline__ void mma16(float4& d,
                                      uint32_t a0, uint32_t a1, uint32_t a2, uint32_t a3,
                                      uint32_t b0, uint32_t b1) {
    asm volatile(
        "mma.sync.aligned.m16n8k16.row.col.f32.f16.f16.f32 "
        "{%0,%1,%2,%3}, {%4,%5,%6,%7}, {%8,%9}, {%0,%1,%2,%3};"
        : "+f"(d.x), "+f"(d.y), "+f"(d.z), "+f"(d.w)
        : "r"(a0), "r"(a1), "r"(a2), "r"(a3), "r"(b0), "r"(b1));
}
__device__ __forceinline__ void ldsm4(uint32_t* r, uint32_t a) {
    asm volatile("ldmatrix.sync.aligned.m8n8.x4.shared.b16 {%0,%1,%2,%3}, [%4];"
                 : "=r"(r[0]), "=r"(r[1]), "=r"(r[2]), "=r"(r[3]) : "r"(a));
}
__device__ __forceinline__ void cpasync16(uint32_t saddr, const void* gptr) {
    asm volatile("cp.async.cg.shared.global [%0], [%1], 16;"
                 :: "r"(saddr), "l"(gptr) : "memory");
}
#define CP_COMMIT() asm volatile("cp.async.commit_group;" ::: "memory")
#define CP_WAIT0()  asm volatile("cp.async.wait_group 0;" ::: "memory")
#define CP_WAIT1()  asm volatile("cp.async.wait_group 1;" ::: "memory")

// ============================================================================
// Kernel 0: one-shot conversions (x->fp16, W->fp16, paired half2 bias tables)
// ============================================================================
#define NX4 1572864   // 8192*768/4
#define NW4 442368    // 2304*768/4
#define NWQ4 147456   // 768*768/4
#define NBT 47628     // 63*63*12 scalars
#define PREP_BLOCKS ((NX4 + NW4 + NBT + 255) / 256)

__global__ __launch_bounds__(256)
void prep(const float* __restrict__ x, const float* __restrict__ Wq,
          const float* __restrict__ Wkv, const float* __restrict__ rb)
{
    const int idx = blockIdx.x * 256 + threadIdx.x;
    if (idx < NX4) {
        float4 v = __ldg((const float4*)x + idx);
        ((uint2*)g_xh)[idx] = make_uint2(h2pack(v.x, v.y), h2pack(v.z, v.w));
    } else if (idx < NX4 + NW4) {
        const int j = idx - NX4;
        const float4* src = (j < NWQ4) ? ((const float4*)Wq + j)
                                       : ((const float4*)Wkv + (j - NWQ4));
        float4 v = __ldg(src);
        ((uint2*)g_wh)[j] = make_uint2(h2pack(v.x, v.y), h2pack(v.z, v.w));
    } else if (idx < NX4 + NW4 + NBT) {
        // rb layout: [(r*63+c)][12]; logical table T[b]=rb*log2e at b=r*64+c
        const int j  = idx - NX4 - NW4;          // = rc*12 + h
        const int rc = j / 12;
        const int h  = j - rc * 12;
        const int r  = rc / 63;
        const int c  = rc - r * 63;
        const int b  = r * 64 + c;
        const __half v = __float2half_rn(__ldg(rb + j) * L2E);
        __half* E = g_btE + h * BHI * 2;
        __half* O = g_btO + h * BHI * 2;
        if ((b & 1) == 0) {
            E[b]     = v;          // E[b/2].lo     = T[b]
            O[b + 1] = v;          // O[b/2].hi     = T[b]
        } else {
            O[b - 1] = v;          // O[(b-1)/2].lo = T[b]
            E[b + 2] = v;          // E[(b+1)/2].hi = T[b]
        }
    }
}

// ============================================================================
// Kernel 1: QKV projection, fp16 m16n8k16, cp.async 3-stage, ldmatrix frags.
// CTA tile 256(M) x 128(N), 512 threads, 16 warps (8M x 2N), warp tile 32x64.
// Halves W L2 traffic and smem write traffic vs 128x128 tiles.
// ============================================================================
#define QA_BYTES 36864u                 // A stage: 256 rows * 36 words * 4
#define QB_BYTES 18432u                 // B stage: 128 rows * 36 words * 4
#define QSTAGE   (QA_BYTES + QB_BYTES)  // 55296
#define QKV_SMEM (3 * QSTAGE)           // 165888

__global__ __launch_bounds__(512, 1)
void qkv_tc(const float* __restrict__ bq, const float* __restrict__ bkv)
{
    extern __shared__ __align__(16) char qraw[];
    const uint32_t sbq = smem_u32(qraw);

    const int tid  = threadIdx.x;
    const int wid  = tid >> 5;
    const int lane = tid & 31;
    const int g    = lane >> 2;
    const int tig  = lane & 3;
    const int mBase = blockIdx.y * 256;
    const int nBase = blockIdx.x * 128;
    const int wm = (wid >> 1) * 32;     // 0..224
    const int wn = (wid & 1) * 64;

    const __half* xh = g_xh;
    const __half* wh = g_wh;

    const int mA = lane >> 3;
    const uint32_t aoff = ((uint32_t)(wm + (mA & 1) * 8 + (lane & 7)) * 36
                           + (uint32_t)(mA >> 1) * 4) * 4;
    const uint32_t boff = ((uint32_t)(wn + (mA >> 1) * 8 + (lane & 7)) * 36
                           + (uint32_t)(mA & 1) * 4) * 4;

#define QISSUE(ch_, s_)                                                          \
    do {                                                                         \
        const uint32_t ad = sbq + (uint32_t)(s_) * QSTAGE;                       \
        const uint32_t bd = ad + QA_BYTES;                                       \
        _Pragma("unroll")                                                        \
        for (int i = 0; i < 4; i++) {                                            \
            const int c = tid + i * 512;                                         \
            const int row = c >> 3, ii = c & 7;                                  \
            cpasync16(ad + (uint32_t)(row * 36 + ii * 4) * 4,                    \
                      xh + (size_t)(mBase + row) * CDIM + (ch_) * 64 + ii * 8);  \
        }                                                                        \
        _Pragma("unroll")                                                        \
        for (int i = 0; i < 2; i++) {                                            \
            const int c = tid + i * 512;                                         \
            const int row = c >> 3, ii = c & 7;                                  \
            cpasync16(bd + (uint32_t)(row * 36 + ii * 4) * 4,                    \
                      wh + (size_t)(nBase + row) * CDIM + (ch_) * 64 + ii * 8);  \
        }                                                                        \
    } while (0)

    float4 dacc[2][8];
#pragma unroll
    for (int mt = 0; mt < 2; mt++)
#pragma unroll
        for (int nt = 0; nt < 8; nt++) dacc[mt][nt] = make_float4(0.f, 0.f, 0.f, 0.f);

    QISSUE(0, 0);
    CP_COMMIT();
    QISSUE(1, 1);
    CP_COMMIT();

    for (int ch = 0; ch < 12; ch++) {
        if (ch < 11) CP_WAIT1(); else CP_WAIT0();
        __syncthreads();
        if (ch < 10) {
            const int nx = ch + 2;
            QISSUE(nx, nx - (nx / 3) * 3);
            CP_COMMIT();
        }

        const int ss = ch - (ch / 3) * 3;
        const uint32_t Aad = sbq + (uint32_t)ss * QSTAGE;
        const uint32_t Bad = Aad + QA_BYTES;
#pragma unroll
        for (int kc = 0; kc < 4; kc++) {
            uint32_t a0[4], a1[4];
            ldsm4(a0, Aad + aoff + kc * 32);
            ldsm4(a1, Aad + aoff + 2304 + kc * 32);   // +16 rows
#pragma unroll
            for (int p = 0; p < 4; p++) {
                uint32_t bf[4];
                ldsm4(bf, Bad + boff + p * 2304 + kc * 32);
                mma16(dacc[0][2*p],   a0[0], a0[1], a0[2], a0[3], bf[0], bf[1]);
                mma16(dacc[0][2*p+1], a0[0], a0[1], a0[2], a0[3], bf[2], bf[3]);
                mma16(dacc[1][2*p],   a1[0], a1[1], a1[2], a1[3], bf[0], bf[1]);
                mma16(dacc[1][2*p+1], a1[0], a1[1], a1[2], a1[3], bf[2], bf[3]);
            }
        }
    }

    const int bidx = mBase >> 10;   // 256-row tile never crosses a batch

    if (nBase < 1536) {
        const int cb = nBase + wn;
        const bool isQ = (cb < 768);
        const float mul = isQ ? (0.125f * L2E) : 1.f;
        const float* brow = isQ ? (bq + cb) : (bkv + (cb - 768));
        __half* dst = isQ ? g_q : g_k;
        const int hh = (cb % 768) >> 6;
        const int bh = bidx * NHEAD + hh;
#pragma unroll
        for (int mt = 0; mt < 2; mt++) {
#pragma unroll
            for (int rr = 0; rr < 2; rr++) {
                const int row = mBase + wm + mt * 16 + g + rr * 8;
                const int tok = row & 1023;
                uint32_t* orow = (uint32_t*)(dst + (size_t)(bh * NTOK + tok) * HDIM);
#pragma unroll
                for (int nt = 0; nt < 8; nt++) {
                    const int dd = nt * 8 + 2 * tig;
                    float v0, v1;
                    if (rr == 0) { v0 = dacc[mt][nt].x; v1 = dacc[mt][nt].y; }
                    else         { v0 = dacc[mt][nt].z; v1 = dacc[mt][nt].w; }
                    v0 = (v0 + __ldg(brow + dd)) * mul;
                    v1 = (v1 + __ldg(brow + dd + 1)) * mul;
                    orow[dd >> 1] = h2pack(v0, v1);
                }
            }
        }
    } else {
        // ---- V: transpose via smem, write g_vT[bh][dim][tok] ----
        __half* Vt = (__half*)qraw;   // [64][264] halves = 33792 B
#pragma unroll
        for (int p = 0; p < 2; p++) {
            if (wn == p * 64) {
                const float* brow = bkv + (nBase + wn - 768);
#pragma unroll
                for (int mt = 0; mt < 2; mt++) {
#pragma unroll
                    for (int rr = 0; rr < 2; rr++) {
                        const int tokl = wm + mt * 16 + g + rr * 8;   // 0..255
#pragma unroll
                        for (int nt = 0; nt < 8; nt++) {
                            const int dd = nt * 8 + 2 * tig;
                            float v0, v1;
                            if (rr == 0) { v0 = dacc[mt][nt].x; v1 = dacc[mt][nt].y; }
                            else         { v0 = dacc[mt][nt].z; v1 = dacc[mt][nt].w; }
                            Vt[dd * 264 + tokl]       = __float2half_rn(v0 + __ldg(brow + dd));
                            Vt[(dd + 1) * 264 + tokl] = __float2half_rn(v1 + __ldg(brow + dd + 1));
                        }
                    }
                }
            }
            __syncthreads();
            const int hp = (nBase + p * 64 - 1536) >> 6;
            const int bh_p = bidx * NHEAD + hp;
            const int d = tid >> 3;              // 0..63
            const int tok0 = (tid & 7) * 32;     // 0..224
            const uint32_t* vtw = (const uint32_t*)Vt;
            uint32_t* odst = (uint32_t*)(g_vT + (size_t)(bh_p * HDIM + d) * NTOK
                                         + (mBase & 1023) + tok0);
#pragma unroll
            for (int i = 0; i < 4; i++) {
                uint4 val = *(const uint4*)(vtw + d * 132 + (tok0 >> 1) + 4 * i);
                *(uint4*)(odst + 4 * i) = val;
            }
            __syncthreads();
        }
    }
}

// ============================================================================
// Kernel 2: flash attention, fp16 m16n8k16, 3-stage cp.async, ldmatrix frags.
// Max-free fp16x2 softmax; row sums via all-ones MMA. (unchanged from R12)
// ============================================================================
#define KW 36                       // smem row stride in u32 words
#define FL_STAGE (2 * 64 * KW * 4)  // bytes per stage (K + V) = 18432
#define FL_SMEM  (3 * FL_STAGE)     // 55296
#define ONES2 0x3C003C00u           // half2(1.0, 1.0)

__global__ __launch_bounds__(256, 2)
void flash_tc(float* __restrict__ out)
{
    extern __shared__ __align__(16) uint32_t fsm[];

    const int tid  = threadIdx.x;
    const int wid  = tid >> 5;
    const int lane = tid & 31;
    const int g    = lane >> 2;
    const int t    = lane & 3;
    const int qt   = blockIdx.x;
    const int bh   = blockIdx.y;
    const int b    = bh / NHEAD;
    const int h    = bh % NHEAD;

    const uint32_t sb = smem_u32(fsm);
    const __half* kbh = g_k  + (size_t)bh * (NTOK * HDIM);
    const __half* vbh = g_vT + (size_t)bh * (HDIM * NTOK);

    // Q A-fragments, register resident
    const int qrow0 = qt * 128 + wid * 16 + g;
    const uint32_t* qw = (const uint32_t*)g_q + (size_t)(bh * NTOK + qrow0) * 32;
    uint32_t qf[4][4];
#pragma unroll
    for (int kc = 0; kc < 4; kc++) {
        qf[kc][0] = __ldg(qw + kc * 8 + t);
        qf[kc][1] = __ldg(qw + 256 + kc * 8 + t);
        qf[kc][2] = __ldg(qw + kc * 8 + t + 4);
        qf[kc][3] = __ldg(qw + 256 + kc * 8 + t + 4);
    }

    const int mA = lane >> 3;
    const uint32_t kvoff = ((uint32_t)((mA >> 1) * 8 + (lane & 7)) * KW
                            + (uint32_t)(mA & 1) * 4) * 4;

    const int qi0 = qrow0 >> 5,       qj0 = qrow0 & 31;
    const int qi1 = (qrow0 + 8) >> 5, qj1 = (qrow0 + 8) & 31;

    // paired-bias setup: gather index parity fixed per thread; pick E/O table
    const int e0 = (qi0 + 31) * 64 + qj0 + 31 - 2 * t;
    const int e1 = (qi1 + 31) * 64 + qj1 + 31 - 2 * t;
    const __half* tb = ((e0 & 1) == 0) ? g_btE : g_btO;
    const uint32_t* bth = (const uint32_t*)(tb + h * BHI * 2);
    const int e0h = e0 >> 1;
    const int e1h = e1 >> 1;

    float4 o[8];
#pragma unroll
    for (int nt = 0; nt < 8; nt++) o[nt] = make_float4(0.f, 0.f, 0.f, 0.f);
    float4 ls = make_float4(0.f, 0.f, 0.f, 0.f);   // row-sum accumulator (ones-MMA)

#define ISSUE_TILE(kt_, s_)                                                     \
    do {                                                                        \
        const uint32_t kd = sb + (uint32_t)(s_) * FL_STAGE;                     \
        const uint32_t vd = kd + (64 * KW * 4);                                 \
        _Pragma("unroll")                                                       \
        for (int c = tid; c < 512; c += 256) {                                  \
            const int row = c >> 3, ii = c & 7;                                 \
            cpasync16(kd + (uint32_t)(row * KW + ii * 4) * 4,                   \
                      kbh + ((kt_) * 64 + row) * 64 + ii * 8);                  \
            cpasync16(vd + (uint32_t)(row * KW + ii * 4) * 4,                   \
                      vbh + row * NTOK + (kt_) * 64 + ii * 8);                  \
        }                                                                       \
    } while (0)

    ISSUE_TILE(0, 0);
    CP_COMMIT();
    ISSUE_TILE(1, 1);
    CP_COMMIT();

    for (int kt = 0; kt < 16; kt++) {
        if (kt < 15) CP_WAIT1(); else CP_WAIT0();
        __syncthreads();
        if (kt < 14) {
            const int nx = kt + 2;
            ISSUE_TILE(nx, nx - (nx / 3) * 3);
            CP_COMMIT();
        }

        const int ss = kt - (kt / 3) * 3;
        const uint32_t Kad = sb + (uint32_t)ss * FL_STAGE;
        const uint32_t Vad = Kad + (64 * KW * 4);

        // ---- S = Q K^T ----
        float4 s[8];
#pragma unroll
        for (int nt = 0; nt < 8; nt++) s[nt] = make_float4(0.f, 0.f, 0.f, 0.f);
#pragma unroll
        for (int kc = 0; kc < 4; kc++) {
#pragma unroll
            for (int p = 0; p < 4; p++) {
                uint32_t bf[4];
                ldsm4(bf, Kad + kvoff + p * 2304 + kc * 32);
                mma16(s[2*p],   qf[kc][0], qf[kc][1], qf[kc][2], qf[kc][3], bf[0], bf[1]);
                mma16(s[2*p+1], qf[kc][0], qf[kc][1], qf[kc][2], qf[kc][3], bf[2], bf[3]);
            }
        }

        // ---- fp16x2 softmax: pack -> +bias(half2) -> ex2.f16x2 ----
        const uint32_t* b0p = bth + (e0h - kt * 64);
        const uint32_t* b1p = bth + (e1h - kt * 64);
        uint32_t pa[4][4];
#pragma unroll
        for (int nt = 0; nt < 8; nt++) {
            const int off = nt * 4 + ((nt >= 4) ? 16 : 0);
            const uint32_t bb0 = __ldg(b0p - off);   // half2 (bias_x, bias_y)
            const uint32_t bb1 = __ldg(b1p - off);
            uint32_t sp0 = ex2h2(hadd2u(h2pack(s[nt].x, s[nt].y), bb0));
            uint32_t sp1 = ex2h2(hadd2u(h2pack(s[nt].z, s[nt].w), bb1));
            const int kc = nt >> 1;
            if ((nt & 1) == 0) { pa[kc][0] = sp0; pa[kc][1] = sp1; }
            else               { pa[kc][2] = sp0; pa[kc][3] = sp1; }
        }

        // ---- O += P V ; row sums via all-ones B fragment ----
#pragma unroll
        for (int kc = 0; kc < 4; kc++) {
            mma16(ls, pa[kc][0], pa[kc][1], pa[kc][2], pa[kc][3], ONES2, ONES2);
#pragma unroll
            for (int p = 0; p < 4; p++) {
                uint32_t bf[4];
                ldsm4(bf, Vad + kvoff + p * 2304 + kc * 32);
                mma16(o[2*p],   pa[kc][0], pa[kc][1], pa[kc][2], pa[kc][3], bf[0], bf[1]);
                mma16(o[2*p+1], pa[kc][0], pa[kc][1], pa[kc][2], pa[kc][3], bf[2], bf[3]);
            }
        }
    }

    // ---- epilogue (row sums already complete in ls.x / ls.z) ----
    const float inv0 = 1.f / ls.x;
    const float inv1 = 1.f / ls.z;
    float* out0 = out + (size_t)(b * NTOK + qrow0) * CDIM + h * HDIM;
    float* out1 = out + (size_t)(b * NTOK + qrow0 + 8) * CDIM + h * HDIM;
#pragma unroll
    for (int nt = 0; nt < 8; nt++) {
        const int dd = nt * 8 + 2 * t;
        *(float2*)(out0 + dd) = make_float2(o[nt].x * inv0, o[nt].y * inv0);
        *(float2*)(out1 + dd) = make_float2(o[nt].z * inv1, o[nt].w * inv1);
    }
}

// ============================================================================
extern "C" void kernel_launch(void* const* d_in, const int* in_sizes, int n_in,
                              void* d_out, int out_size)
{
    const float* x        = (const float*)d_in[0];
    const float* Wq       = (const float*)d_in[1];
    const float* bq       = (const float*)d_in[2];
    const float* Wkv      = (const float*)d_in[3];
    const float* bkv      = (const float*)d_in[4];
    const float* rel_bias = (const float*)d_in[5];
    float* out = (float*)d_out;

    prep<<<PREP_BLOCKS, 256>>>(x, Wq, Wkv, rel_bias);

    cudaFuncSetAttribute(qkv_tc, cudaFuncAttributeMaxDynamicSharedMemorySize,
                         QKV_SMEM);
    qkv_tc<<<dim3(NTOTC / 128, MROWS / 256), 512, QKV_SMEM>>>(bq, bkv);

    cudaFuncSetAttribute(flash_tc, cudaFuncAttributeMaxDynamicSharedMemorySize,
                         FL_SMEM);
    flash_tc<<<dim3(8, BATCH * NHEAD), 256, FL_SMEM>>>(out);
}

// round 14
// speedup vs baseline: 1.0555x; 1.0555x over previous
#include <cuda_runtime.h>
#include <cuda_fp16.h>
#include <math.h>
#include <stdint.h>

#define BATCH 8
#define NTOK  1024
#define CDIM  768
#define NHEAD 12
#define HDIM  64
#define NTOTC 2304
#define MROWS 8192
#define L2E   1.44269504f

// -------- device-global scratch --------
__device__ __align__(16) __half g_xh[MROWS * CDIM];          // fp16 x
__device__ __align__(16) __half g_wh[NTOTC * CDIM];          // fp16 [Wq; Wkv]
// half2 paired bias tables (pre-scaled by log2e):
//  E[h][i] = (lo=T[2i],   hi=T[2i-1])   (for even gather index b)
//  O[h][i] = (lo=T[2i+1], hi=T[2i])     (for odd  gather index b)
#define BHI 2048
__device__ __align__(16) __half g_btE[NHEAD * BHI * 2];
__device__ __align__(16) __half g_btO[NHEAD * BHI * 2];
__device__ __align__(16) __half g_q [BATCH * NHEAD * NTOK * HDIM];  // pre-scaled by 0.125*log2e
__device__ __align__(16) __half g_k [BATCH * NHEAD * NTOK * HDIM];
__device__ __align__(16) __half g_vT[BATCH * NHEAD * HDIM * NTOK];  // [bh][dim][tok]

// ============================================================================
// helpers
// ============================================================================
__device__ __forceinline__ uint32_t smem_u32(const void* p) {
    uint32_t a;
    asm("{ .reg .u64 t; cvta.to.shared.u64 t, %1; cvt.u32.u64 %0, t; }"
        : "=r"(a) : "l"(p));
    return a;
}
__device__ __forceinline__ uint32_t h2pack(float a, float b) {
    __half2 h = __floats2half2_rn(a, b);
    return *reinterpret_cast<uint32_t*>(&h);
}
__device__ __forceinline__ uint32_t hadd2u(uint32_t a, uint32_t b) {
    uint32_t r;
    asm("add.f16x2 %0, %1, %2;" : "=r"(r) : "r"(a), "r"(b));
    return r;
}
__device__ __forceinline__ uint32_t ex2h2(uint32_t a) {
    uint32_t r;
    asm("ex2.approx.f16x2 %0, %1;" : "=r"(r) : "r"(a));
    return r;
}
__device__ __forceinline__ void mma16(float4& d,
                                      uint32_t a0, uint32_t a1, uint32_t a2, uint32_t a3,
                                      uint32_t b0, uint32_t b1) {
    asm volatile(
        "mma.sync.aligned.m16n8k16.row.col.f32.f16.f16.f32 "
        "{%0,%1,%2,%3}, {%4,%5,%6,%7}, {%8,%9}, {%0,%1,%2,%3};"
        : "+f"(d.x), "+f"(d.y), "+f"(d.z), "+f"(d.w)
        : "r"(a0), "r"(a1), "r"(a2), "r"(a3), "r"(b0), "r"(b1));
}
__device__ __forceinline__ void ldsm4(uint32_t* r, uint32_t a) {
    asm volatile("ldmatrix.sync.aligned.m8n8.x4.shared.b16 {%0,%1,%2,%3}, [%4];"
                 : "=r"(r[0]), "=r"(r[1]), "=r"(r[2]), "=r"(r[3]) : "r"(a));
}
__device__ __forceinline__ void cpasync16(uint32_t saddr, const void* gptr) {
    asm volatile("cp.async.cg.shared.global [%0], [%1], 16;"
                 :: "r"(saddr), "l"(gptr) : "memory");
}
#define CP_COMMIT() asm volatile("cp.async.commit_group;" ::: "memory")
#define CP_WAIT0()  asm volatile("cp.async.wait_group 0;" ::: "memory")
#define CP_WAIT1()  asm volatile("cp.async.wait_group 1;" ::: "memory")

// ============================================================================
// Kernel 0: one-shot conversions (x->fp16, W->fp16, paired half2 bias tables)
// ============================================================================
#define NX4 1572864   // 8192*768/4
#define NW4 442368    // 2304*768/4
#define NWQ4 147456   // 768*768/4
#define NBT 47628     // 63*63*12 scalars
#define PREP_BLOCKS ((NX4 + NW4 + NBT + 255) / 256)

__global__ __launch_bounds__(256)
void prep(const float* __restrict__ x, const float* __restrict__ Wq,
          const float* __restrict__ Wkv, const float* __restrict__ rb)
{
    const int idx = blockIdx.x * 256 + threadIdx.x;
    if (idx < NX4) {
        float4 v = __ldg((const float4*)x + idx);
        ((uint2*)g_xh)[idx] = make_uint2(h2pack(v.x, v.y), h2pack(v.z, v.w));
    } else if (idx < NX4 + NW4) {
        const int j = idx - NX4;
        const float4* src = (j < NWQ4) ? ((const float4*)Wq + j)
                                       : ((const float4*)Wkv + (j - NWQ4));
        float4 v = __ldg(src);
        ((uint2*)g_wh)[j] = make_uint2(h2pack(v.x, v.y), h2pack(v.z, v.w));
    } else if (idx < NX4 + NW4 + NBT) {
        // rb layout: [(r*63+c)][12]; logical table T[b]=rb*log2e at b=r*64+c
        const int j  = idx - NX4 - NW4;          // = rc*12 + h
        const int rc = j / 12;
        const int h  = j - rc * 12;
        const int r  = rc / 63;
        const int c  = rc - r * 63;
        const int b  = r * 64 + c;
        const __half v = __float2half_rn(__ldg(rb + j) * L2E);
        __half* E = g_btE + h * BHI * 2;
        __half* O = g_btO + h * BHI * 2;
        if ((b & 1) == 0) {
            E[b]     = v;          // E[b/2].lo     = T[b]
            O[b + 1] = v;          // O[b/2].hi     = T[b]
        } else {
            O[b - 1] = v;          // O[(b-1)/2].lo = T[b]
            E[b + 2] = v;          // E[(b+1)/2].hi = T[b]
        }
    }
}

// ============================================================================
// Kernel 1: QKV projection, fp16 m16n8k16, cp.async 3-stage, ldmatrix frags.
// CTA 128x128, 256 threads, 2 CTAs/SM. (R12 configuration — best measured)
// ============================================================================
#define QSTAGE 36864u
#define QKV_SMEM (3 * QSTAGE)

__global__ __launch_bounds__(256, 2)
void qkv_tc(const float* __restrict__ bq, const float* __restrict__ bkv)
{
    extern __shared__ __align__(16) char qraw[];
    const uint32_t sbq = smem_u32(qraw);

    const int tid  = threadIdx.x;
    const int wid  = tid >> 5;
    const int lane = tid & 31;
    const int g    = lane >> 2;
    const int tig  = lane & 3;
    const int mBase = blockIdx.y * 128;
    const int nBase = blockIdx.x * 128;
    const int wm = (wid >> 1) * 32;
    const int wn = (wid & 1) * 64;

    const __half* xh = g_xh;
    const __half* wh = g_wh;

    const int mA = lane >> 3;
    const uint32_t aoff = ((uint32_t)(wm + (mA & 1) * 8 + (lane & 7)) * 36
                           + (uint32_t)(mA >> 1) * 4) * 4;
    const uint32_t boff = ((uint32_t)(wn + (mA >> 1) * 8 + (lane & 7)) * 36
                           + (uint32_t)(mA & 1) * 4) * 4;

#define QISSUE(ch_, s_)                                                          \
    do {                                                                         \
        const uint32_t ad = sbq + (uint32_t)(s_) * QSTAGE;                       \
        const uint32_t bd = ad + 18432u;                                         \
        _Pragma("unroll")                                                        \
        for (int i = 0; i < 4; i++) {                                            \
            const int c = tid + i * 256;                                         \
            const int row = c >> 3, ii = c & 7;                                  \
            cpasync16(ad + (uint32_t)(row * 36 + ii * 4) * 4,                    \
                      xh + (size_t)(mBase + row) * CDIM + (ch_) * 64 + ii * 8);  \
            cpasync16(bd + (uint32_t)(row * 36 + ii * 4) * 4,                    \
                      wh + (size_t)(nBase + row) * CDIM + (ch_) * 64 + ii * 8);  \
        }                                                                        \
    } while (0)

    float4 dacc[2][8];
#pragma unroll
    for (int mt = 0; mt < 2; mt++)
#pragma unroll
        for (int nt = 0; nt < 8; nt++) dacc[mt][nt] = make_float4(0.f, 0.f, 0.f, 0.f);

    QISSUE(0, 0);
    CP_COMMIT();
    QISSUE(1, 1);
    CP_COMMIT();

    for (int ch = 0; ch < 12; ch++) {
        if (ch < 11) CP_WAIT1(); else CP_WAIT0();
        __syncthreads();
        if (ch < 10) {
            const int nx = ch + 2;
            QISSUE(nx, nx - (nx / 3) * 3);
            CP_COMMIT();
        }

        const int ss = ch - (ch / 3) * 3;
        const uint32_t Aad = sbq + (uint32_t)ss * QSTAGE;
        const uint32_t Bad = Aad + 18432u;
#pragma unroll
        for (int kc = 0; kc < 4; kc++) {
            uint32_t a0[4], a1[4];
            ldsm4(a0, Aad + aoff + kc * 32);
            ldsm4(a1, Aad + aoff + 2304 + kc * 32);
#pragma unroll
            for (int p = 0; p < 4; p++) {
                uint32_t bf[4];
                ldsm4(bf, Bad + boff + p * 2304 + kc * 32);
                mma16(dacc[0][2*p],   a0[0], a0[1], a0[2], a0[3], bf[0], bf[1]);
                mma16(dacc[0][2*p+1], a0[0], a0[1], a0[2], a0[3], bf[2], bf[3]);
                mma16(dacc[1][2*p],   a1[0], a1[1], a1[2], a1[3], bf[0], bf[1]);
                mma16(dacc[1][2*p+1], a1[0], a1[1], a1[2], a1[3], bf[2], bf[3]);
            }
        }
    }

    const int bidx = mBase >> 10;

    if (nBase < 1536) {
        const int cb = nBase + wn;
        const bool isQ = (cb < 768);
        const float mul = isQ ? (0.125f * L2E) : 1.f;
        const float* brow = isQ ? (bq + cb) : (bkv + (cb - 768));
        __half* dst = isQ ? g_q : g_k;
        const int hh = (cb % 768) >> 6;
        const int bh = bidx * NHEAD + hh;
#pragma unroll
        for (int mt = 0; mt < 2; mt++) {
#pragma unroll
            for (int rr = 0; rr < 2; rr++) {
                const int row = mBase + wm + mt * 16 + g + rr * 8;
                const int tok = row & 1023;
                uint32_t* orow = (uint32_t*)(dst + (size_t)(bh * NTOK + tok) * HDIM);
#pragma unroll
                for (int nt = 0; nt < 8; nt++) {
                    const int dd = nt * 8 + 2 * tig;
                    float v0, v1;
                    if (rr == 0) { v0 = dacc[mt][nt].x; v1 = dacc[mt][nt].y; }
                    else         { v0 = dacc[mt][nt].z; v1 = dacc[mt][nt].w; }
                    v0 = (v0 + __ldg(brow + dd)) * mul;
                    v1 = (v1 + __ldg(brow + dd + 1)) * mul;
                    orow[dd >> 1] = h2pack(v0, v1);
                }
            }
        }
    } else {
        __half* Vt = (__half*)qraw;   // [64][136] halves
#pragma unroll
        for (int p = 0; p < 2; p++) {
            if (wn == p * 64) {
                const float* brow = bkv + (nBase + wn - 768);
#pragma unroll
                for (int mt = 0; mt < 2; mt++) {
#pragma unroll
                    for (int rr = 0; rr < 2; rr++) {
                        const int tokl = wm + mt * 16 + g + rr * 8;
#pragma unroll
                        for (int nt = 0; nt < 8; nt++) {
                            const int dd = nt * 8 + 2 * tig;
                            float v0, v1;
                            if (rr == 0) { v0 = dacc[mt][nt].x; v1 = dacc[mt][nt].y; }
                            else         { v0 = dacc[mt][nt].z; v1 = dacc[mt][nt].w; }
                            Vt[dd * 136 + tokl]       = __float2half_rn(v0 + __ldg(brow + dd));
                            Vt[(dd + 1) * 136 + tokl] = __float2half_rn(v1 + __ldg(brow + dd + 1));
                        }
                    }
                }
            }
            __syncthreads();
            const int hp = (nBase + p * 64 - 1536) >> 6;
            const int bh_p = bidx * NHEAD + hp;
            const int d = tid >> 2;
            const int tok0 = (tid & 3) * 32;
            const uint32_t* vtw = (const uint32_t*)Vt;
            uint32_t* odst = (uint32_t*)(g_vT + (size_t)(bh_p * HDIM + d) * NTOK
                                         + (mBase & 1023) + tok0);
#pragma unroll
            for (int i = 0; i < 4; i++) {
                uint4 val = *(const uint4*)(vtw + d * 68 + (tok0 >> 1) + 4 * i);
                *(uint4*)(odst + 4 * i) = val;
            }
            __syncthreads();
        }
    }
}

// ============================================================================
// Kernel 2: flash attention, fp16 m16n8k16. 128-kv-row tiles (8 outer iters,
// half the barriers/waits), 2-stage cp.async double buffer, computed in two
// 64-kv halves. Max-free fp16x2 softmax; row sums via all-ones MMA.
// ============================================================================
#define KROW 144u                   // K tile row stride bytes (64 dims + pad)
#define VROW 272u                   // V tile row stride bytes (128 toks + pad)
#define FK_BYTES (128 * KROW)       // 18432
#define FV_BYTES (64 * VROW)        // 17408
#define FL_STAGE (FK_BYTES + FV_BYTES)  // 35840
#define FL_SMEM  (2 * FL_STAGE)         // 71680
#define ONES2 0x3C003C00u           // half2(1.0, 1.0)

__global__ __launch_bounds__(256, 2)
void flash_tc(float* __restrict__ out)
{
    extern __shared__ __align__(16) uint32_t fsm[];

    const int tid  = threadIdx.x;
    const int wid  = tid >> 5;
    const int lane = tid & 31;
    const int g    = lane >> 2;
    const int t    = lane & 3;
    const int qt   = blockIdx.x;
    const int bh   = blockIdx.y;
    const int b    = bh / NHEAD;
    const int h    = bh % NHEAD;

    const uint32_t sb = smem_u32(fsm);
    const __half* kbh = g_k  + (size_t)bh * (NTOK * HDIM);
    const __half* vbh = g_vT + (size_t)bh * (HDIM * NTOK);

    // Q A-fragments, register resident
    const int qrow0 = qt * 128 + wid * 16 + g;
    const uint32_t* qw = (const uint32_t*)g_q + (size_t)(bh * NTOK + qrow0) * 32;
    uint32_t qf[4][4];
#pragma unroll
    for (int kc = 0; kc < 4; kc++) {
        qf[kc][0] = __ldg(qw + kc * 8 + t);
        qf[kc][1] = __ldg(qw + 256 + kc * 8 + t);
        qf[kc][2] = __ldg(qw + kc * 8 + t + 4);
        qf[kc][3] = __ldg(qw + 256 + kc * 8 + t + 4);
    }

    const int mA = lane >> 3;
    const uint32_t koff = (uint32_t)((mA >> 1) * 8 + (lane & 7)) * KROW
                        + (uint32_t)(mA & 1) * 16;
    const uint32_t voff = (uint32_t)((mA >> 1) * 8 + (lane & 7)) * VROW
                        + (uint32_t)(mA & 1) * 16;

    const int qi0 = qrow0 >> 5,       qj0 = qrow0 & 31;
    const int qi1 = (qrow0 + 8) >> 5, qj1 = (qrow0 + 8) & 31;

    // paired-bias setup: gather index parity fixed per thread; pick E/O table
    const int e0 = (qi0 + 31) * 64 + qj0 + 31 - 2 * t;
    const int e1 = (qi1 + 31) * 64 + qj1 + 31 - 2 * t;
    const __half* tb = ((e0 & 1) == 0) ? g_btE : g_btO;
    const uint32_t* bth = (const uint32_t*)(tb + h * BHI * 2);
    const int e0h = e0 >> 1;
    const int e1h = e1 >> 1;

    float4 o[8];
#pragma unroll
    for (int nt = 0; nt < 8; nt++) o[nt] = make_float4(0.f, 0.f, 0.f, 0.f);
    float4 ls = make_float4(0.f, 0.f, 0.f, 0.f);   // row-sum accumulator (ones-MMA)

    // Big-tile issue: K = 128 kv rows x 64 dims, V = 64 dim rows x 128 toks.
#define ISSUE_TILE(kt2_, s_)                                                    \
    do {                                                                        \
        const uint32_t kd = sb + (uint32_t)(s_) * FL_STAGE;                     \
        const uint32_t vd = kd + FK_BYTES;                                      \
        _Pragma("unroll")                                                       \
        for (int i = 0; i < 4; i++) {                                           \
            const int c = tid + i * 256;                                        \
            const int krow = c >> 3, kii = c & 7;                               \
            cpasync16(kd + (uint32_t)krow * KROW + (uint32_t)kii * 16,          \
                      kbh + ((kt2_) * 128 + krow) * 64 + kii * 8);              \
            const int vrow = c >> 4, vii = c & 15;                              \
            cpasync16(vd + (uint32_t)vrow * VROW + (uint32_t)vii * 16,          \
                      vbh + vrow * NTOK + (kt2_) * 128 + vii * 8);              \
        }                                                                       \
    } while (0)

    ISSUE_TILE(0, 0);
    CP_COMMIT();

    for (int kt2 = 0; kt2 < 8; kt2++) {
        CP_WAIT0();
        __syncthreads();   // cp data visible + previous buffer fully consumed
        if (kt2 < 7) { ISSUE_TILE(kt2 + 1, (kt2 + 1) & 1); CP_COMMIT(); }

        const uint32_t Kad0 = sb + (uint32_t)(kt2 & 1) * FL_STAGE;
        const uint32_t Vad  = Kad0 + FK_BYTES;

#pragma unroll
        for (int half = 0; half < 2; half++) {
            const int kt = kt2 * 2 + half;
            const uint32_t Kad = Kad0 + (uint32_t)half * (64 * KROW);

            // ---- S = Q K^T ----
            float4 s[8];
#pragma unroll
            for (int nt = 0; nt < 8; nt++) s[nt] = make_float4(0.f, 0.f, 0.f, 0.f);
#pragma unroll
            for (int kc = 0; kc < 4; kc++) {
#pragma unroll
                for (int p = 0; p < 4; p++) {
                    uint32_t bf[4];
                    ldsm4(bf, Kad + koff + p * (16 * KROW) + kc * 32);
                    mma16(s[2*p],   qf[kc][0], qf[kc][1], qf[kc][2], qf[kc][3], bf[0], bf[1]);
                    mma16(s[2*p+1], qf[kc][0], qf[kc][1], qf[kc][2], qf[kc][3], bf[2], bf[3]);
                }
            }

            // ---- fp16x2 softmax: pack -> +bias(half2) -> ex2.f16x2 ----
            const uint32_t* b0p = bth + (e0h - kt * 64);
            const uint32_t* b1p = bth + (e1h - kt * 64);
            uint32_t pa[4][4];
#pragma unroll
            for (int nt = 0; nt < 8; nt++) {
                const int off = nt * 4 + ((nt >= 4) ? 16 : 0);
                const uint32_t bb0 = __ldg(b0p - off);   // half2 (bias_x, bias_y)
                const uint32_t bb1 = __ldg(b1p - off);
                uint32_t sp0 = ex2h2(hadd2u(h2pack(s[nt].x, s[nt].y), bb0));
                uint32_t sp1 = ex2h2(hadd2u(h2pack(s[nt].z, s[nt].w), bb1));
                const int kc = nt >> 1;
                if ((nt & 1) == 0) { pa[kc][0] = sp0; pa[kc][1] = sp1; }
                else               { pa[kc][2] = sp0; pa[kc][3] = sp1; }
            }

            // ---- O += P V ; row sums via all-ones B fragment ----
#pragma unroll
            for (int kc = 0; kc < 4; kc++) {
                mma16(ls, pa[kc][0], pa[kc][1], pa[kc][2], pa[kc][3], ONES2, ONES2);
                const uint32_t vk = voff + (uint32_t)(half * 128 + kc * 32);
#pragma unroll
                for (int p = 0; p < 4; p++) {
                    uint32_t bf[4];
                    ldsm4(bf, Vad + vk + p * (16 * VROW));
                    mma16(o[2*p],   pa[kc][0], pa[kc][1], pa[kc][2], pa[kc][3], bf[0], bf[1]);
                    mma16(o[2*p+1], pa[kc][0], pa[kc][1], pa[kc][2], pa[kc][3], bf[2], bf[3]);
                }
            }
        }
    }

    // ---- epilogue (row sums already complete in ls.x / ls.z) ----
    const float inv0 = 1.f / ls.x;
    const float inv1 = 1.f / ls.z;
    float* out0 = out + (size_t)(b * NTOK + qrow0) * CDIM + h * HDIM;
    float* out1 = out + (size_t)(b * NTOK + qrow0 + 8) * CDIM + h * HDIM;
#pragma unroll
    for (int nt = 0; nt < 8; nt++) {
        const int dd = nt * 8 + 2 * t;
        *(float2*)(out0 + dd) = make_float2(o[nt].x * inv0, o[nt].y * inv0);
        *(float2*)(out1 + dd) = make_float2(o[nt].z * inv1, o[nt].w * inv1);
    }
}

// ============================================================================
extern "C" void kernel_launch(void* const* d_in, const int* in_sizes, int n_in,
                              void* d_out, int out_size)
{
    const float* x        = (const float*)d_in[0];
    const float* Wq       = (const float*)d_in[1];
    const float* bq       = (const float*)d_in[2];
    const float* Wkv      = (const float*)d_in[3];
    const float* bkv      = (const float*)d_in[4];
    const float* rel_bias = (const float*)d_in[5];
    float* out = (float*)d_out;

    prep<<<PREP_BLOCKS, 256>>>(x, Wq, Wkv, rel_bias);

    cudaFuncSetAttribute(qkv_tc, cudaFuncAttributeMaxDynamicSharedMemorySize,
                         QKV_SMEM);
    qkv_tc<<<dim3(NTOTC / 128, MROWS / 128), 256, QKV_SMEM>>>(bq, bkv);

    cudaFuncSetAttribute(flash_tc, cudaFuncAttributeMaxDynamicSharedMemorySize,
                         FL_SMEM);
    flash_tc<<<dim3(8, BATCH * NHEAD), 256, FL_SMEM>>>(out);
}

// round 15
// speedup vs baseline: 1.0855x; 1.0284x over previous
#include <cuda_runtime.h>
#include <cuda_fp16.h>
#include <math.h>
#include <stdint.h>

#define BATCH 8
#define NTOK  1024
#define CDIM  768
#define NHEAD 12
#define HDIM  64
#define NTOTC 2304
#define MROWS 8192
#define L2E   1.44269504f

// -------- device-global scratch --------
__device__ __align__(16) __half g_xh[MROWS * CDIM];          // fp16 x
__device__ __align__(16) __half g_wh[NTOTC * CDIM];          // fp16 [Wq; Wkv]
// half2 paired bias tables (pre-scaled by log2e):
//  E[h][i] = (lo=T[2i],   hi=T[2i-1])   (for even gather index b)
//  O[h][i] = (lo=T[2i+1], hi=T[2i])     (for odd  gather index b)
#define BHI 2048
__device__ __align__(16) __half g_btE[NHEAD * BHI * 2];
__device__ __align__(16) __half g_btO[NHEAD * BHI * 2];
__device__ __align__(16) __half g_q [BATCH * NHEAD * NTOK * HDIM];  // pre-scaled by 0.125*log2e
__device__ __align__(16) __half g_k [BATCH * NHEAD * NTOK * HDIM];
__device__ __align__(16) __half g_vT[BATCH * NHEAD * HDIM * NTOK];  // [bh][dim][tok]

// ============================================================================
// helpers
// ============================================================================
__device__ __forceinline__ uint32_t smem_u32(const void* p) {
    uint32_t a;
    asm("{ .reg .u64 t; cvta.to.shared.u64 t, %1; cvt.u32.u64 %0, t; }"
        : "=r"(a) : "l"(p));
    return a;
}
__device__ __forceinline__ uint32_t h2pack(float a, float b) {
    __half2 h = __floats2half2_rn(a, b);
    return *reinterpret_cast<uint32_t*>(&h);
}
__device__ __forceinline__ uint32_t hadd2u(uint32_t a, uint32_t b) {
    uint32_t r;
    asm("add.f16x2 %0, %1, %2;" : "=r"(r) : "r"(a), "r"(b));
    return r;
}
__device__ __forceinline__ uint32_t ex2h2(uint32_t a) {
    uint32_t r;
    asm("ex2.approx.f16x2 %0, %1;" : "=r"(r) : "r"(a));
    return r;
}
__device__ __forceinline__ void mma16(float4& d,
                                      uint32_t a0, uint32_t a1, uint32_t a2, uint32_t a3,
                                      uint32_t b0, uint32_t b1) {
    asm volatile(
        "mma.sync.aligned.m16n8k16.row.col.f32.f16.f16.f32 "
        "{%0,%1,%2,%3}, {%4,%5,%6,%7}, {%8,%9}, {%0,%1,%2,%3};"
        : "+f"(d.x), "+f"(d.y), "+f"(d.z), "+f"(d.w)
        : "r"(a0), "r"(a1), "r"(a2), "r"(a3), "r"(b0), "r"(b1));
}
__device__ __forceinline__ void ldsm4(uint32_t* r, uint32_t a) {
    asm volatile("ldmatrix.sync.aligned.m8n8.x4.shared.b16 {%0,%1,%2,%3}, [%4];"
                 : "=r"(r[0]), "=r"(r[1]), "=r"(r[2]), "=r"(r[3]) : "r"(a));
}
__device__ __forceinline__ void cpasync16(uint32_t saddr, const void* gptr) {
    asm volatile("cp.async.cg.shared.global [%0], [%1], 16;"
                 :: "r"(saddr), "l"(gptr) : "memory");
}
#define CP_COMMIT() asm volatile("cp.async.commit_group;" ::: "memory")
#define CP_WAIT0()  asm volatile("cp.async.wait_group 0;" ::: "memory")
#define CP_WAIT1()  asm volatile("cp.async.wait_group 1;" ::: "memory")

// ============================================================================
// Kernel 0: one-shot conversions (x->fp16, W->fp16, paired half2 bias tables)
// ============================================================================
#define NX4 1572864   // 8192*768/4
#define NW4 442368    // 2304*768/4
#define NWQ4 147456   // 768*768/4
#define NBT 47628     // 63*63*12 scalars
#define PREP_BLOCKS ((NX4 + NW4 + NBT + 255) / 256)

__global__ __launch_bounds__(256)
void prep(const float* __restrict__ x, const float* __restrict__ Wq,
          const float* __restrict__ Wkv, const float* __restrict__ rb)
{
    const int idx = blockIdx.x * 256 + threadIdx.x;
    if (idx < NX4) {
        float4 v = __ldg((const float4*)x + idx);
        ((uint2*)g_xh)[idx] = make_uint2(h2pack(v.x, v.y), h2pack(v.z, v.w));
    } else if (idx < NX4 + NW4) {
        const int j = idx - NX4;
        const float4* src = (j < NWQ4) ? ((const float4*)Wq + j)
                                       : ((const float4*)Wkv + (j - NWQ4));
        float4 v = __ldg(src);
        ((uint2*)g_wh)[j] = make_uint2(h2pack(v.x, v.y), h2pack(v.z, v.w));
    } else if (idx < NX4 + NW4 + NBT) {
        // rb layout: [(r*63+c)][12]; logical table T[b]=rb*log2e at b=r*64+c
        const int j  = idx - NX4 - NW4;          // = rc*12 + h
        const int rc = j / 12;
        const int h  = j - rc * 12;
        const int r  = rc / 63;
        const int c  = rc - r * 63;
        const int b  = r * 64 + c;
        const __half v = __float2half_rn(__ldg(rb + j) * L2E);
        __half* E = g_btE + h * BHI * 2;
        __half* O = g_btO + h * BHI * 2;
        if ((b & 1) == 0) {
            E[b]     = v;          // E[b/2].lo     = T[b]
            O[b + 1] = v;          // O[b/2].hi     = T[b]
        } else {
            O[b - 1] = v;          // O[(b-1)/2].lo = T[b]
            E[b + 2] = v;          // E[(b+1)/2].hi = T[b]
        }
    }
}

// ============================================================================
// Kernel 1: QKV projection, fp16 m16n8k16, cp.async 3-stage, ldmatrix frags.
// CTA 128x128, 256 threads, 2 CTAs/SM. (best measured configuration)
// ============================================================================
#define QSTAGE 36864u
#define QKV_SMEM (3 * QSTAGE)

__global__ __launch_bounds__(256, 2)
void qkv_tc(const float* __restrict__ bq, const float* __restrict__ bkv)
{
    extern __shared__ __align__(16) char qraw[];
    const uint32_t sbq = smem_u32(qraw);

    const int tid  = threadIdx.x;
    const int wid  = tid >> 5;
    const int lane = tid & 31;
    const int g    = lane >> 2;
    const int tig  = lane & 3;
    const int mBase = blockIdx.y * 128;
    const int nBase = blockIdx.x * 128;
    const int wm = (wid >> 1) * 32;
    const int wn = (wid & 1) * 64;

    const __half* xh = g_xh;
    const __half* wh = g_wh;

    const int mA = lane >> 3;
    const uint32_t aoff = ((uint32_t)(wm + (mA & 1) * 8 + (lane & 7)) * 36
                           + (uint32_t)(mA >> 1) * 4) * 4;
    const uint32_t boff = ((uint32_t)(wn + (mA >> 1) * 8 + (lane & 7)) * 36
                           + (uint32_t)(mA & 1) * 4) * 4;

#define QISSUE(ch_, s_)                                                          \
    do {                                                                         \
        const uint32_t ad = sbq + (uint32_t)(s_) * QSTAGE;                       \
        const uint32_t bd = ad + 18432u;                                         \
        _Pragma("unroll")                                                        \
        for (int i = 0; i < 4; i++) {                                            \
            const int c = tid + i * 256;                                         \
            const int row = c >> 3, ii = c & 7;                                  \
            cpasync16(ad + (uint32_t)(row * 36 + ii * 4) * 4,                    \
                      xh + (size_t)(mBase + row) * CDIM + (ch_) * 64 + ii * 8);  \
            cpasync16(bd + (uint32_t)(row * 36 + ii * 4) * 4,                    \
                      wh + (size_t)(nBase + row) * CDIM + (ch_) * 64 + ii * 8);  \
        }                                                                        \
    } while (0)

    float4 dacc[2][8];
#pragma unroll
    for (int mt = 0; mt < 2; mt++)
#pragma unroll
        for (int nt = 0; nt < 8; nt++) dacc[mt][nt] = make_float4(0.f, 0.f, 0.f, 0.f);

    QISSUE(0, 0);
    CP_COMMIT();
    QISSUE(1, 1);
    CP_COMMIT();

    for (int ch = 0; ch < 12; ch++) {
        if (ch < 11) CP_WAIT1(); else CP_WAIT0();
        __syncthreads();
        if (ch < 10) {
            const int nx = ch + 2;
            QISSUE(nx, nx - (nx / 3) * 3);
            CP_COMMIT();
        }

        const int ss = ch - (ch / 3) * 3;
        const uint32_t Aad = sbq + (uint32_t)ss * QSTAGE;
        const uint32_t Bad = Aad + 18432u;
#pragma unroll
        for (int kc = 0; kc < 4; kc++) {
            uint32_t a0[4], a1[4];
            ldsm4(a0, Aad + aoff + kc * 32);
            ldsm4(a1, Aad + aoff + 2304 + kc * 32);
#pragma unroll
            for (int p = 0; p < 4; p++) {
                uint32_t bf[4];
                ldsm4(bf, Bad + boff + p * 2304 + kc * 32);
                mma16(dacc[0][2*p],   a0[0], a0[1], a0[2], a0[3], bf[0], bf[1]);
                mma16(dacc[0][2*p+1], a0[0], a0[1], a0[2], a0[3], bf[2], bf[3]);
                mma16(dacc[1][2*p],   a1[0], a1[1], a1[2], a1[3], bf[0], bf[1]);
                mma16(dacc[1][2*p+1], a1[0], a1[1], a1[2], a1[3], bf[2], bf[3]);
            }
        }
    }

    const int bidx = mBase >> 10;

    if (nBase < 1536) {
        const int cb = nBase + wn;
        const bool isQ = (cb < 768);
        const float mul = isQ ? (0.125f * L2E) : 1.f;
        const float* brow = isQ ? (bq + cb) : (bkv + (cb - 768));
        __half* dst = isQ ? g_q : g_k;
        const int hh = (cb % 768) >> 6;
        const int bh = bidx * NHEAD + hh;
#pragma unroll
        for (int mt = 0; mt < 2; mt++) {
#pragma unroll
            for (int rr = 0; rr < 2; rr++) {
                const int row = mBase + wm + mt * 16 + g + rr * 8;
                const int tok = row & 1023;
                uint32_t* orow = (uint32_t*)(dst + (size_t)(bh * NTOK + tok) * HDIM);
#pragma unroll
                for (int nt = 0; nt < 8; nt++) {
                    const int dd = nt * 8 + 2 * tig;
                    float v0, v1;
                    if (rr == 0) { v0 = dacc[mt][nt].x; v1 = dacc[mt][nt].y; }
                    else         { v0 = dacc[mt][nt].z; v1 = dacc[mt][nt].w; }
                    v0 = (v0 + __ldg(brow + dd)) * mul;
                    v1 = (v1 + __ldg(brow + dd + 1)) * mul;
                    orow[dd >> 1] = h2pack(v0, v1);
                }
            }
        }
    } else {
        __half* Vt = (__half*)qraw;   // [64][136] halves
#pragma unroll
        for (int p = 0; p < 2; p++) {
            if (wn == p * 64) {
                const float* brow = bkv + (nBase + wn - 768);
#pragma unroll
                for (int mt = 0; mt < 2; mt++) {
#pragma unroll
                    for (int rr = 0; rr < 2; rr++) {
                        const int tokl = wm + mt * 16 + g + rr * 8;
#pragma unroll
                        for (int nt = 0; nt < 8; nt++) {
                            const int dd = nt * 8 + 2 * tig;
                            float v0, v1;
                            if (rr == 0) { v0 = dacc[mt][nt].x; v1 = dacc[mt][nt].y; }
                            else         { v0 = dacc[mt][nt].z; v1 = dacc[mt][nt].w; }
                            Vt[dd * 136 + tokl]       = __float2half_rn(v0 + __ldg(brow + dd));
                            Vt[(dd + 1) * 136 + tokl] = __float2half_rn(v1 + __ldg(brow + dd + 1));
                        }
                    }
                }
            }
            __syncthreads();
            const int hp = (nBase + p * 64 - 1536) >> 6;
            const int bh_p = bidx * NHEAD + hp;
            const int d = tid >> 2;
            const int tok0 = (tid & 3) * 32;
            const uint32_t* vtw = (const uint32_t*)Vt;
            uint32_t* odst = (uint32_t*)(g_vT + (size_t)(bh_p * HDIM + d) * NTOK
                                         + (mBase & 1023) + tok0);
#pragma unroll
            for (int i = 0; i < 4; i++) {
                uint4 val = *(const uint4*)(vtw + d * 68 + (tok0 >> 1) + 4 * i);
                *(uint4*)(odst + 4 * i) = val;
            }
            __syncthreads();
        }
    }
}

// ============================================================================
// Kernel 2: flash attention, fp16 m16n8k16. 32 q-rows per warp (256 q/CTA),
// halving per-q-row K/V fragment smem reads (one ldsm feeds 4 MMAs).
// 128-kv-row tiles, 2-stage cp.async, max-free fp16x2 softmax, ones-MMA sums.
// Grid (4, 96), 256 threads, 1 CTA/SM (high register usage).
// ============================================================================
#define KROW 144u                   // K tile row stride bytes (64 dims + pad)
#define VROW 272u                   // V tile row stride bytes (128 toks + pad)
#define FK_BYTES (128 * KROW)       // 18432
#define FV_BYTES (64 * VROW)        // 17408
#define FL_STAGE (FK_BYTES + FV_BYTES)  // 35840
#define FL_SMEM  (2 * FL_STAGE)         // 71680
#define ONES2 0x3C003C00u           // half2(1.0, 1.0)

__global__ __launch_bounds__(256, 1)
void flash_tc(float* __restrict__ out)
{
    extern __shared__ __align__(16) uint32_t fsm[];

    const int tid  = threadIdx.x;
    const int wid  = tid >> 5;
    const int lane = tid & 31;
    const int g    = lane >> 2;
    const int t    = lane & 3;
    const int qt   = blockIdx.x;            // 0..3 (256 q rows per CTA)
    const int bh   = blockIdx.y;
    const int b    = bh / NHEAD;
    const int h    = bh % NHEAD;

    const uint32_t sb = smem_u32(fsm);
    const __half* kbh = g_k  + (size_t)bh * (NTOK * HDIM);
    const __half* vbh = g_vT + (size_t)bh * (HDIM * NTOK);

    // Q A-fragments for 32 rows (2 m-blocks), register resident
    const int qrow0 = qt * 256 + wid * 32 + g;
    const uint32_t* qw = (const uint32_t*)g_q + (size_t)(bh * NTOK + qrow0) * 32;
    uint32_t qf[2][4][4];
#pragma unroll
    for (int mb = 0; mb < 2; mb++) {
        const uint32_t* qm = qw + mb * 512;   // +16 rows
#pragma unroll
        for (int kc = 0; kc < 4; kc++) {
            qf[mb][kc][0] = __ldg(qm + kc * 8 + t);
            qf[mb][kc][1] = __ldg(qm + 256 + kc * 8 + t);
            qf[mb][kc][2] = __ldg(qm + kc * 8 + t + 4);
            qf[mb][kc][3] = __ldg(qm + 256 + kc * 8 + t + 4);
        }
    }

    const int mA = lane >> 3;
    const uint32_t koff = (uint32_t)((mA >> 1) * 8 + (lane & 7)) * KROW
                        + (uint32_t)(mA & 1) * 16;
    const uint32_t voff = (uint32_t)((mA >> 1) * 8 + (lane & 7)) * VROW
                        + (uint32_t)(mA & 1) * 16;

    // bias setup per m-block (parity identical across mb: row deltas keep qj parity)
    int e0h[2], e1h[2];
#pragma unroll
    for (int mb = 0; mb < 2; mb++) {
        const int r0 = qrow0 + 16 * mb;
        const int qi0 = r0 >> 5,       qj0 = r0 & 31;
        const int qi1 = (r0 + 8) >> 5, qj1 = (r0 + 8) & 31;
        e0h[mb] = ((qi0 + 31) * 64 + qj0 + 31 - 2 * t) >> 1;
        e1h[mb] = ((qi1 + 31) * 64 + qj1 + 31 - 2 * t) >> 1;
    }
    const int epar = ((qrow0 >> 5) + 31) * 64 + (qrow0 & 31) + 31 - 2 * t;
    const __half* tb = ((epar & 1) == 0) ? g_btE : g_btO;
    const uint32_t* bth = (const uint32_t*)(tb + h * BHI * 2);

    float4 o[2][8];
#pragma unroll
    for (int mb = 0; mb < 2; mb++)
#pragma unroll
        for (int nt = 0; nt < 8; nt++) o[mb][nt] = make_float4(0.f, 0.f, 0.f, 0.f);
    float4 ls[2];
    ls[0] = make_float4(0.f, 0.f, 0.f, 0.f);
    ls[1] = make_float4(0.f, 0.f, 0.f, 0.f);

#define ISSUE_TILE(kt2_, s_)                                                    \
    do {                                                                        \
        const uint32_t kd = sb + (uint32_t)(s_) * FL_STAGE;                     \
        const uint32_t vd = kd + FK_BYTES;                                      \
        _Pragma("unroll")                                                       \
        for (int i = 0; i < 4; i++) {                                           \
            const int c = tid + i * 256;                                        \
            const int krow = c >> 3, kii = c & 7;                               \
            cpasync16(kd + (uint32_t)krow * KROW + (uint32_t)kii * 16,          \
                      kbh + ((kt2_) * 128 + krow) * 64 + kii * 8);              \
            const int vrow = c >> 4, vii = c & 15;                              \
            cpasync16(vd + (uint32_t)vrow * VROW + (uint32_t)vii * 16,          \
                      vbh + vrow * NTOK + (kt2_) * 128 + vii * 8);              \
        }                                                                       \
    } while (0)

    ISSUE_TILE(0, 0);
    CP_COMMIT();

    for (int kt2 = 0; kt2 < 8; kt2++) {
        CP_WAIT0();
        __syncthreads();
        if (kt2 < 7) { ISSUE_TILE(kt2 + 1, (kt2 + 1) & 1); CP_COMMIT(); }

        const uint32_t Kad0 = sb + (uint32_t)(kt2 & 1) * FL_STAGE;
        const uint32_t Vad  = Kad0 + FK_BYTES;

#pragma unroll
        for (int half = 0; half < 2; half++) {
            const int kt = kt2 * 2 + half;
            const uint32_t Kad = Kad0 + (uint32_t)half * (64 * KROW);

            // ---- S = Q K^T (one K ldsm feeds 4 MMAs) ----
            float4 s[2][8];
#pragma unroll
            for (int mb = 0; mb < 2; mb++)
#pragma unroll
                for (int nt = 0; nt < 8; nt++) s[mb][nt] = make_float4(0.f, 0.f, 0.f, 0.f);
#pragma unroll
            for (int kc = 0; kc < 4; kc++) {
#pragma unroll
                for (int p = 0; p < 4; p++) {
                    uint32_t bf[4];
                    ldsm4(bf, Kad + koff + p * (16 * KROW) + kc * 32);
#pragma unroll
                    for (int mb = 0; mb < 2; mb++) {
                        mma16(s[mb][2*p],   qf[mb][kc][0], qf[mb][kc][1],
                              qf[mb][kc][2], qf[mb][kc][3], bf[0], bf[1]);
                        mma16(s[mb][2*p+1], qf[mb][kc][0], qf[mb][kc][1],
                              qf[mb][kc][2], qf[mb][kc][3], bf[2], bf[3]);
                    }
                }
            }

            // ---- fp16x2 softmax: pack -> +bias(half2) -> ex2.f16x2 ----
            uint32_t pa[2][4][4];
#pragma unroll
            for (int mb = 0; mb < 2; mb++) {
                const uint32_t* b0p = bth + (e0h[mb] - kt * 64);
                const uint32_t* b1p = bth + (e1h[mb] - kt * 64);
#pragma unroll
                for (int nt = 0; nt < 8; nt++) {
                    const int off = nt * 4 + ((nt >= 4) ? 16 : 0);
                    const uint32_t bb0 = __ldg(b0p - off);
                    const uint32_t bb1 = __ldg(b1p - off);
                    uint32_t sp0 = ex2h2(hadd2u(h2pack(s[mb][nt].x, s[mb][nt].y), bb0));
                    uint32_t sp1 = ex2h2(hadd2u(h2pack(s[mb][nt].z, s[mb][nt].w), bb1));
                    const int kc = nt >> 1;
                    if ((nt & 1) == 0) { pa[mb][kc][0] = sp0; pa[mb][kc][1] = sp1; }
                    else               { pa[mb][kc][2] = sp0; pa[mb][kc][3] = sp1; }
                }
            }

            // ---- O += P V ; row sums via all-ones B fragment ----
#pragma unroll
            for (int kc = 0; kc < 4; kc++) {
                mma16(ls[0], pa[0][kc][0], pa[0][kc][1], pa[0][kc][2], pa[0][kc][3], ONES2, ONES2);
                mma16(ls[1], pa[1][kc][0], pa[1][kc][1], pa[1][kc][2], pa[1][kc][3], ONES2, ONES2);
                const uint32_t vk = voff + (uint32_t)(half * 128 + kc * 32);
#pragma unroll
                for (int p = 0; p < 4; p++) {
                    uint32_t bf[4];
                    ldsm4(bf, Vad + vk + p * (16 * VROW));
#pragma unroll
                    for (int mb = 0; mb < 2; mb++) {
                        mma16(o[mb][2*p],   pa[mb][kc][0], pa[mb][kc][1],
                              pa[mb][kc][2], pa[mb][kc][3], bf[0], bf[1]);
                        mma16(o[mb][2*p+1], pa[mb][kc][0], pa[mb][kc][1],
                              pa[mb][kc][2], pa[mb][kc][3], bf[2], bf[3]);
                    }
                }
            }
        }
    }

    // ---- epilogue ----
#pragma unroll
    for (int mb = 0; mb < 2; mb++) {
        const float inv0 = 1.f / ls[mb].x;
        const float inv1 = 1.f / ls[mb].z;
        const int r0 = qrow0 + 16 * mb;
        float* out0 = out + (size_t)(b * NTOK + r0) * CDIM + h * HDIM;
        float* out1 = out + (size_t)(b * NTOK + r0 + 8) * CDIM + h * HDIM;
#pragma unroll
        for (int nt = 0; nt < 8; nt++) {
            const int dd = nt * 8 + 2 * t;
            *(float2*)(out0 + dd) = make_float2(o[mb][nt].x * inv0, o[mb][nt].y * inv0);
            *(float2*)(out1 + dd) = make_float2(o[mb][nt].z * inv1, o[mb][nt].w * inv1);
        }
    }
}

// ============================================================================
extern "C" void kernel_launch(void* const* d_in, const int* in_sizes, int n_in,
                              void* d_out, int out_size)
{
    const float* x        = (const float*)d_in[0];
    const float* Wq       = (const float*)d_in[1];
    const float* bq       = (const float*)d_in[2];
    const float* Wkv      = (const float*)d_in[3];
    const float* bkv      = (const float*)d_in[4];
    const float* rel_bias = (const float*)d_in[5];
    float* out = (float*)d_out;

    prep<<<PREP_BLOCKS, 256>>>(x, Wq, Wkv, rel_bias);

    cudaFuncSetAttribute(qkv_tc, cudaFuncAttributeMaxDynamicSharedMemorySize,
                         QKV_SMEM);
    qkv_tc<<<dim3(NTOTC / 128, MROWS / 128), 256, QKV_SMEM>>>(bq, bkv);

    cudaFuncSetAttribute(flash_tc, cudaFuncAttributeMaxDynamicSharedMemorySize,
                         FL_SMEM);
    flash_tc<<<dim3(4, BATCH * NHEAD), 256, FL_SMEM>>>(out);
}